// round 2
// baseline (speedup 1.0000x reference)
#include <cuda_runtime.h>
#include <cuda_fp16.h>

// AWQ int4 dequant + GEMM, fused. Harness widens fp16 tensors to fp32.
//   A:      f32 [M=4096, K=4096]   (hidden_states, B*S flattened; exact f16 values)
//   qw:     int32 [K, N/8]          nibble j of word -> column p*8+j
//   scales: f32 [K/128, N]          (exact f16 values)
//   C:      f32 [M, N=11008]
// C[m][n] = sum_k A[m][k] * (nib(qw,k,n) - 8) * scales[k/128][n]

#define BM 128
#define BN 128
#define BK 32

static constexpr int K_DIM  = 4096;
static constexpr int N_DIM  = 11008;
static constexpr int GROUP  = 128;
static constexpr int PACKED_N = N_DIM / 8;   // 1376

__device__ __forceinline__ unsigned smem_u32(const void* p) {
    return (unsigned)__cvta_generic_to_shared(p);
}

#define LDMATRIX_X4(r0, r1, r2, r3, addr)                                     \
    asm volatile("ldmatrix.sync.aligned.m8n8.x4.shared.b16 {%0,%1,%2,%3}, [%4];" \
                 : "=r"(r0), "=r"(r1), "=r"(r2), "=r"(r3) : "r"(addr))

#define LDMATRIX_X4_T(r0, r1, r2, r3, addr)                                   \
    asm volatile("ldmatrix.sync.aligned.m8n8.x4.trans.shared.b16 {%0,%1,%2,%3}, [%4];" \
                 : "=r"(r0), "=r"(r1), "=r"(r2), "=r"(r3) : "r"(addr))

#define MMA_16816(d0, d1, d2, d3, a0, a1, a2, a3, b0, b1)                     \
    asm volatile("mma.sync.aligned.m16n8k16.row.col.f32.f16.f16.f32 "         \
                 "{%0,%1,%2,%3}, {%4,%5,%6,%7}, {%8,%9}, {%0,%1,%2,%3};"       \
                 : "+f"(d0), "+f"(d1), "+f"(d2), "+f"(d3)                      \
                 : "r"(a0), "r"(a1), "r"(a2), "r"(a3), "r"(b0), "r"(b1))

__global__ __launch_bounds__(256, 2)
void awq_gemm_kernel(const float* __restrict__ A,
                     const int*   __restrict__ qw,
                     const float* __restrict__ scales,
                     float*       __restrict__ C)
{
    __shared__ __align__(16) half sA[BM][BK + 8];   // row stride 80B (16B multiple)
    __shared__ __align__(16) half sB[BK][BN + 8];   // row stride 272B (16B multiple)

    const int tid    = threadIdx.x;
    const int lane   = tid & 31;
    const int wid    = tid >> 5;
    const int warp_m = wid & 1;   // 0..1 -> 64-row slab
    const int warp_n = wid >> 1;  // 0..3 -> 32-col slab

    const int m0 = blockIdx.y * BM;
    const int n0 = blockIdx.x * BN;

    // qweight tile assignment: 32 k-rows x 16 int32-cols; thread does rows q_row, q_row+16
    const int q_col = tid & 15;   // int32 column within tile (8 outputs each)
    const int q_row = tid >> 4;   // 0..15

    float acc[4][4][4];
    #pragma unroll
    for (int i = 0; i < 4; i++)
        #pragma unroll
        for (int j = 0; j < 4; j++)
            #pragma unroll
            for (int l = 0; l < 4; l++) acc[i][j][l] = 0.0f;

    const half2 MAGIC = __halves2half2(__ushort_as_half(0x6408), __ushort_as_half(0x6408)); // 1032

    const int* qw_base = qw + (size_t)q_row * PACKED_N + (n0 >> 3) + q_col;

    for (int k0 = 0; k0 < K_DIM; k0 += BK) {
        __syncthreads();   // all warps done reading sA/sB from previous iter

        // ---- A (f32) -> convert f16 -> smem.  128 rows x 32 floats = 1024 float4 chunks.
        #pragma unroll
        for (int i = 0; i < 4; i++) {
            int c   = tid + i * 256;
            int row = c >> 3;
            int col = (c & 7) * 4;
            float4 v = *reinterpret_cast<const float4*>(
                A + (size_t)(m0 + row) * K_DIM + k0 + col);
            uint2 h;
            half2 h01 = __floats2half2_rn(v.x, v.y);
            half2 h23 = __floats2half2_rn(v.z, v.w);
            h.x = *reinterpret_cast<unsigned*>(&h01);
            h.y = *reinterpret_cast<unsigned*>(&h23);
            *reinterpret_cast<uint2*>(&sA[row][col]) = h;   // 8B aligned
        }

        // ---- qweight + scales (f32) -> dequant -> sB ----
        {
            const int* qp = qw_base + (size_t)k0 * PACKED_N;
            int q0 = qp[0];
            int q1 = qp[(size_t)16 * PACKED_N];

            const int g = k0 / GROUP;
            const float* sp = scales + (size_t)g * N_DIM + n0 + q_col * 8;
            float4 f0 = *reinterpret_cast<const float4*>(sp);      // cols 0..3
            float4 f1 = *reinterpret_cast<const float4*>(sp + 4);  // cols 4..7
            half2 sc[4];
            sc[0] = __floats2half2_rn(f0.x, f1.x);   // (col0, col4)
            sc[1] = __floats2half2_rn(f0.y, f1.y);   // (col1, col5)
            sc[2] = __floats2half2_rn(f0.z, f1.z);   // (col2, col6)
            sc[3] = __floats2half2_rn(f0.w, f1.w);   // (col3, col7)

            #pragma unroll
            for (int half_idx = 0; half_idx < 2; half_idx++) {
                unsigned q = (half_idx == 0) ? (unsigned)q0 : (unsigned)q1;
                unsigned t0 = ( q         & 0x000F000Fu) | 0x64006400u; // (n0, n4)
                unsigned t1 = ((q >> 4)   & 0x000F000Fu) | 0x64006400u; // (n1, n5)
                unsigned t2 = ((q >> 8)   & 0x000F000Fu) | 0x64006400u; // (n2, n6)
                unsigned t3 = ((q >> 12)  & 0x000F000Fu) | 0x64006400u; // (n3, n7)
                half2 v0 = __hmul2(__hsub2(*reinterpret_cast<half2*>(&t0), MAGIC), sc[0]);
                half2 v1 = __hmul2(__hsub2(*reinterpret_cast<half2*>(&t1), MAGIC), sc[1]);
                half2 v2 = __hmul2(__hsub2(*reinterpret_cast<half2*>(&t2), MAGIC), sc[2]);
                half2 v3 = __hmul2(__hsub2(*reinterpret_cast<half2*>(&t3), MAGIC), sc[3]);
                // reorder (lo0..lo3, hi0..hi3) -> columns 0..7
                half2 p01 = __halves2half2(__low2half(v0),  __low2half(v1));
                half2 p23 = __halves2half2(__low2half(v2),  __low2half(v3));
                half2 p45 = __halves2half2(__high2half(v0), __high2half(v1));
                half2 p67 = __halves2half2(__high2half(v2), __high2half(v3));
                uint4 packed;
                packed.x = *reinterpret_cast<unsigned*>(&p01);
                packed.y = *reinterpret_cast<unsigned*>(&p23);
                packed.z = *reinterpret_cast<unsigned*>(&p45);
                packed.w = *reinterpret_cast<unsigned*>(&p67);
                *reinterpret_cast<uint4*>(&sB[q_row + half_idx * 16][q_col * 8]) = packed;
            }
        }

        __syncthreads();   // sA and sB ready

        // ---- MMA over BK=32 (2 k-steps of 16) ----
        #pragma unroll
        for (int ks = 0; ks < 2; ks++) {
            unsigned a[4][4];
            #pragma unroll
            for (int mf = 0; mf < 4; mf++) {
                int row = warp_m * 64 + mf * 16 + (lane & 15);
                int col = ks * 16 + (lane >> 4) * 8;
                unsigned addr = smem_u32(&sA[row][col]);
                LDMATRIX_X4(a[mf][0], a[mf][1], a[mf][2], a[mf][3], addr);
            }
            unsigned b[4][2];
            #pragma unroll
            for (int p = 0; p < 2; p++) {
                int row = ks * 16 + (lane & 15);
                int col = warp_n * 32 + p * 16 + (lane >> 4) * 8;
                unsigned addr = smem_u32(&sB[row][col]);
                unsigned r0, r1, r2, r3;
                LDMATRIX_X4_T(r0, r1, r2, r3, addr);
                b[p * 2 + 0][0] = r0; b[p * 2 + 0][1] = r1;
                b[p * 2 + 1][0] = r2; b[p * 2 + 1][1] = r3;
            }
            #pragma unroll
            for (int mf = 0; mf < 4; mf++)
                #pragma unroll
                for (int nf = 0; nf < 4; nf++)
                    MMA_16816(acc[mf][nf][0], acc[mf][nf][1], acc[mf][nf][2], acc[mf][nf][3],
                              a[mf][0], a[mf][1], a[mf][2], a[mf][3],
                              b[nf][0], b[nf][1]);
        }
    }

    // ---- epilogue: fp32 acc -> round to f16 grid (match reference) -> f32 stores ----
    const int r  = lane >> 2;
    const int cp = (lane & 3) * 2;
    #pragma unroll
    for (int mf = 0; mf < 4; mf++) {
        const int row_base = m0 + warp_m * 64 + mf * 16;
        #pragma unroll
        for (int nf = 0; nf < 4; nf++) {
            const int col = n0 + warp_n * 32 + nf * 8 + cp;
            float2 lo, hi;
            lo.x = __half2float(__float2half_rn(acc[mf][nf][0]));
            lo.y = __half2float(__float2half_rn(acc[mf][nf][1]));
            hi.x = __half2float(__float2half_rn(acc[mf][nf][2]));
            hi.y = __half2float(__float2half_rn(acc[mf][nf][3]));
            *reinterpret_cast<float2*>(C + (size_t)(row_base + r)     * N_DIM + col) = lo;
            *reinterpret_cast<float2*>(C + (size_t)(row_base + r + 8) * N_DIM + col) = hi;
        }
    }
}

extern "C" void kernel_launch(void* const* d_in, const int* in_sizes, int n_in,
                              void* d_out, int out_size)
{
    const float* A      = (const float*)d_in[0];
    const int*   qw     = (const int*)d_in[1];
    const float* scales = (const float*)d_in[2];
    float*       C      = (float*)d_out;

    const int m_total = in_sizes[0] / K_DIM;   // 4096
    dim3 grid(N_DIM / BN, m_total / BM);       // (86, 32)
    awq_gemm_kernel<<<grid, 256>>>(A, qw, scales, C);
}

// round 3
// speedup vs baseline: 1.2491x; 1.2491x over previous
#include <cuda_runtime.h>
#include <cuda_fp16.h>

// AWQ int4 dequant + GEMM, fused, 2-stage pipelined HMMA.
//   A:      f32 [M=4096, K=4096]  (pre-converted to f16 scratch by prepass kernel)
//   qw:     int32 [K, N/8]        nibble j of word -> column p*8+j
//   scales: f32 [K/128, N]
//   C:      f32 [M, N=11008]     (values rounded to f16 grid to match reference)

#define BM 128
#define BN 128
#define BK 32

static constexpr int K_DIM    = 4096;
static constexpr int N_DIM    = 11008;
static constexpr int M_TOTAL  = 4096;
static constexpr int PACKED_N = N_DIM / 8;   // 1376

// f16 copy of A, produced once per launch by the prepass kernel.
__device__ __align__(16) half g_A16[(size_t)M_TOTAL * K_DIM];

__device__ __forceinline__ unsigned smem_u32(const void* p) {
    return (unsigned)__cvta_generic_to_shared(p);
}

#define LDMATRIX_X4(r0, r1, r2, r3, addr)                                     \
    asm volatile("ldmatrix.sync.aligned.m8n8.x4.shared.b16 {%0,%1,%2,%3}, [%4];" \
                 : "=r"(r0), "=r"(r1), "=r"(r2), "=r"(r3) : "r"(addr))

#define LDMATRIX_X4_T(r0, r1, r2, r3, addr)                                   \
    asm volatile("ldmatrix.sync.aligned.m8n8.x4.trans.shared.b16 {%0,%1,%2,%3}, [%4];" \
                 : "=r"(r0), "=r"(r1), "=r"(r2), "=r"(r3) : "r"(addr))

#define MMA_16816(d0, d1, d2, d3, a0, a1, a2, a3, b0, b1)                     \
    asm volatile("mma.sync.aligned.m16n8k16.row.col.f32.f16.f16.f32 "         \
                 "{%0,%1,%2,%3}, {%4,%5,%6,%7}, {%8,%9}, {%0,%1,%2,%3};"       \
                 : "+f"(d0), "+f"(d1), "+f"(d2), "+f"(d3)                      \
                 : "r"(a0), "r"(a1), "r"(a2), "r"(a3), "r"(b0), "r"(b1))

// ---------------- prepass: A f32 -> f16 ----------------
__global__ void convert_A_kernel(const float* __restrict__ A)
{
    size_t idx = ((size_t)blockIdx.x * blockDim.x + threadIdx.x) * 8;
    float4 v0 = *reinterpret_cast<const float4*>(A + idx);
    float4 v1 = *reinterpret_cast<const float4*>(A + idx + 4);
    uint4 h;
    half2 a = __floats2half2_rn(v0.x, v0.y);
    half2 b = __floats2half2_rn(v0.z, v0.w);
    half2 c = __floats2half2_rn(v1.x, v1.y);
    half2 d = __floats2half2_rn(v1.z, v1.w);
    h.x = *reinterpret_cast<unsigned*>(&a);
    h.y = *reinterpret_cast<unsigned*>(&b);
    h.z = *reinterpret_cast<unsigned*>(&c);
    h.w = *reinterpret_cast<unsigned*>(&d);
    *reinterpret_cast<uint4*>(g_A16 + idx) = h;
}

// ---------------- main GEMM ----------------
__global__ __launch_bounds__(256, 2)
void awq_gemm_kernel(const int*   __restrict__ qw,
                     const float* __restrict__ scales,
                     float*       __restrict__ C)
{
    __shared__ __align__(16) half sA[2][BM][BK + 8];   // 80B row stride -> r*5 mod 8 perm, conflict-free ldmatrix
    __shared__ __align__(16) half sB[2][BK][BN + 8];   // 272B row stride -> r mod 8 perm, conflict-free

    const int tid    = threadIdx.x;
    const int lane   = tid & 31;
    const int wid    = tid >> 5;
    const int warp_m = wid & 1;
    const int warp_n = wid >> 1;

    const int m0 = blockIdx.y * BM;
    const int n0 = blockIdx.x * BN;

    const int q_col = tid & 15;   // int32 column within tile
    const int q_row = tid >> 4;   // 0..15 (owns rows q_row, q_row+16)

    float acc[4][4][4];
    #pragma unroll
    for (int i = 0; i < 4; i++)
        #pragma unroll
        for (int j = 0; j < 4; j++)
            #pragma unroll
            for (int l = 0; l < 4; l++) acc[i][j][l] = 0.0f;

    const half2 MAGIC = __halves2half2(__ushort_as_half(0x6408), __ushort_as_half(0x6408)); // 1032

    const int*   qw_base = qw + (size_t)q_row * PACKED_N + (n0 >> 3) + q_col;
    const float* sc_base = scales + n0 + q_col * 8;

    half2 sc[4];
    // A-tile cp.async: 512 x 16B chunks, 2 per thread
    const int a_row0 = tid >> 2;          // chunk row for chunk id = tid
    const int a_col0 = (tid & 3) * 8;

#define ISSUE_A(k0, buf)                                                       \
    do {                                                                       \
        unsigned d0 = smem_u32(&sA[buf][a_row0][a_col0]);                      \
        const half* s0 = g_A16 + (size_t)(m0 + a_row0) * K_DIM + (k0) + a_col0; \
        asm volatile("cp.async.cg.shared.global [%0], [%1], 16;\n" :: "r"(d0), "l"(s0)); \
        unsigned d1 = smem_u32(&sA[buf][a_row0 + 64][a_col0]);                 \
        const half* s1 = g_A16 + (size_t)(m0 + a_row0 + 64) * K_DIM + (k0) + a_col0; \
        asm volatile("cp.async.cg.shared.global [%0], [%1], 16;\n" :: "r"(d1), "l"(s1)); \
        asm volatile("cp.async.commit_group;\n");                              \
    } while (0)

#define LOAD_SCALES(g)                                                         \
    do {                                                                       \
        const float* sp = sc_base + (size_t)(g) * N_DIM;                       \
        float4 f0 = *reinterpret_cast<const float4*>(sp);                      \
        float4 f1 = *reinterpret_cast<const float4*>(sp + 4);                  \
        sc[0] = __floats2half2_rn(f0.x, f1.x);                                 \
        sc[1] = __floats2half2_rn(f0.y, f1.y);                                 \
        sc[2] = __floats2half2_rn(f0.z, f1.z);                                 \
        sc[3] = __floats2half2_rn(f0.w, f1.w);                                 \
    } while (0)

#define DEQUANT_STORE(qv, rrow, buf)                                           \
    do {                                                                       \
        unsigned q = (unsigned)(qv);                                           \
        unsigned t0 = ( q        & 0x000F000Fu) | 0x64006400u;                 \
        unsigned t1 = ((q >> 4)  & 0x000F000Fu) | 0x64006400u;                 \
        unsigned t2 = ((q >> 8)  & 0x000F000Fu) | 0x64006400u;                 \
        unsigned t3 = ((q >> 12) & 0x000F000Fu) | 0x64006400u;                 \
        half2 v0 = __hmul2(__hsub2(*reinterpret_cast<half2*>(&t0), MAGIC), sc[0]); \
        half2 v1 = __hmul2(__hsub2(*reinterpret_cast<half2*>(&t1), MAGIC), sc[1]); \
        half2 v2 = __hmul2(__hsub2(*reinterpret_cast<half2*>(&t2), MAGIC), sc[2]); \
        half2 v3 = __hmul2(__hsub2(*reinterpret_cast<half2*>(&t3), MAGIC), sc[3]); \
        half2 p01 = __halves2half2(__low2half(v0),  __low2half(v1));           \
        half2 p23 = __halves2half2(__low2half(v2),  __low2half(v3));           \
        half2 p45 = __halves2half2(__high2half(v0), __high2half(v1));          \
        half2 p67 = __halves2half2(__high2half(v2), __high2half(v3));          \
        uint4 packed;                                                          \
        packed.x = *reinterpret_cast<unsigned*>(&p01);                         \
        packed.y = *reinterpret_cast<unsigned*>(&p23);                         \
        packed.z = *reinterpret_cast<unsigned*>(&p45);                         \
        packed.w = *reinterpret_cast<unsigned*>(&p67);                         \
        *reinterpret_cast<uint4*>(&sB[buf][rrow][q_col * 8]) = packed;         \
    } while (0)

    // ---- prologue: fill stage 0 ----
    ISSUE_A(0, 0);
    {
        int q0 = qw_base[0];
        int q1 = qw_base[(size_t)16 * PACKED_N];
        LOAD_SCALES(0);
        DEQUANT_STORE(q0, q_row, 0);
        DEQUANT_STORE(q1, q_row + 16, 0);
    }
    asm volatile("cp.async.wait_group 0;\n");
    __syncthreads();

    int cur = 0;
    for (int k0 = 0; k0 < K_DIM; k0 += BK) {
        const int k1  = k0 + BK;
        const int nxt = cur ^ 1;
        const bool has_next = (k1 < K_DIM);

        int nq0 = 0, nq1 = 0;
        if (has_next) {
            ISSUE_A(k1, nxt);
            const int* qp = qw_base + (size_t)k1 * PACKED_N;
            nq0 = qp[0];
            nq1 = qp[(size_t)16 * PACKED_N];
        }

        // ---- MMA on current stage ----
        #pragma unroll
        for (int ks = 0; ks < 2; ks++) {
            unsigned a[4][4];
            #pragma unroll
            for (int mf = 0; mf < 4; mf++) {
                int row = warp_m * 64 + mf * 16 + (lane & 15);
                int col = ks * 16 + (lane >> 4) * 8;
                unsigned addr = smem_u32(&sA[cur][row][col]);
                LDMATRIX_X4(a[mf][0], a[mf][1], a[mf][2], a[mf][3], addr);
            }
            unsigned b[4][2];
            #pragma unroll
            for (int p = 0; p < 2; p++) {
                int row = ks * 16 + (lane & 15);
                int col = warp_n * 32 + p * 16 + (lane >> 4) * 8;
                unsigned addr = smem_u32(&sB[cur][row][col]);
                unsigned r0, r1, r2, r3;
                LDMATRIX_X4_T(r0, r1, r2, r3, addr);
                b[p * 2 + 0][0] = r0; b[p * 2 + 0][1] = r1;
                b[p * 2 + 1][0] = r2; b[p * 2 + 1][1] = r3;
            }
            #pragma unroll
            for (int mf = 0; mf < 4; mf++)
                #pragma unroll
                for (int nf = 0; nf < 4; nf++)
                    MMA_16816(acc[mf][nf][0], acc[mf][nf][1], acc[mf][nf][2], acc[mf][nf][3],
                              a[mf][0], a[mf][1], a[mf][2], a[mf][3],
                              b[nf][0], b[nf][1]);
        }

        // ---- produce next stage's B; drain next A ----
        if (has_next) {
            if ((k1 & 127) == 0) LOAD_SCALES(k1 >> 7);
            DEQUANT_STORE(nq0, q_row, nxt);
            DEQUANT_STORE(nq1, q_row + 16, nxt);
            asm volatile("cp.async.wait_group 0;\n");
        }
        __syncthreads();
        cur = nxt;
    }

    // ---- epilogue: round to f16 grid, store f32 ----
    const int r  = lane >> 2;
    const int cp = (lane & 3) * 2;
    #pragma unroll
    for (int mf = 0; mf < 4; mf++) {
        const int row_base = m0 + warp_m * 64 + mf * 16;
        #pragma unroll
        for (int nf = 0; nf < 4; nf++) {
            const int col = n0 + warp_n * 32 + nf * 8 + cp;
            float2 lo, hi;
            lo.x = __half2float(__float2half_rn(acc[mf][nf][0]));
            lo.y = __half2float(__float2half_rn(acc[mf][nf][1]));
            hi.x = __half2float(__float2half_rn(acc[mf][nf][2]));
            hi.y = __half2float(__float2half_rn(acc[mf][nf][3]));
            *reinterpret_cast<float2*>(C + (size_t)(row_base + r)     * N_DIM + col) = lo;
            *reinterpret_cast<float2*>(C + (size_t)(row_base + r + 8) * N_DIM + col) = hi;
        }
    }
}

extern "C" void kernel_launch(void* const* d_in, const int* in_sizes, int n_in,
                              void* d_out, int out_size)
{
    const float* A      = (const float*)d_in[0];
    const int*   qw     = (const int*)d_in[1];
    const float* scales = (const float*)d_in[2];
    float*       C      = (float*)d_out;

    // prepass: A f32 -> f16 (2048 elems per block of 256 threads)
    const size_t total  = (size_t)M_TOTAL * K_DIM;
    convert_A_kernel<<<(unsigned)(total / 2048), 256>>>(A);

    dim3 grid(N_DIM / BN, M_TOTAL / BM);   // (86, 32)
    awq_gemm_kernel<<<grid, 256>>>(qw, scales, C);
}

// round 6
// speedup vs baseline: 1.3248x; 1.0606x over previous
#include <cuda_runtime.h>
#include <cuda_fp16.h>
#include <cstdint>

// AWQ int4 dequant + GEMM, fused, 2-stage pipelined HMMA, BK=64.
//   A:      f32 [M=4096, K=4096]  -> prepass converts to f16 g_A16
//   qw:     int32 [K, N/8]         nibble j of word -> column p*8+j
//   scales: f32 [K/128, N]
//   C:      f32 [M, N=11008]      (values rounded to f16 grid)

#define BM 128
#define BN 128
#define BK 64

static constexpr int K_DIM    = 4096;
static constexpr int N_DIM    = 11008;
static constexpr int M_TOTAL  = 4096;
static constexpr int PACKED_N = N_DIM / 8;   // 1376
static constexpr int K_TILES  = K_DIM / BK;  // 64

// dynamic smem layout (bytes):
//   sA: 2 x 128 x 72 halves  (row stride 144B)  -> 2 x 18432
//   sB: 2 x  64 x 136 halves (row stride 272B)  -> 2 x 17408
static constexpr int SA_STAGE   = 128 * 72 * 2;       // 18432
static constexpr int SB_BASE    = 2 * SA_STAGE;       // 36864
static constexpr int SB_STAGE   = 64 * 136 * 2;       // 17408
static constexpr int SMEM_TOTAL = SB_BASE + 2 * SB_STAGE;  // 71680

__device__ __align__(16) half g_A16[(size_t)M_TOTAL * K_DIM];

__device__ __forceinline__ unsigned smem_u32(const void* p) {
    return (unsigned)__cvta_generic_to_shared(p);
}

#define LDMATRIX_X4(r0, r1, r2, r3, addr)                                     \
    asm volatile("ldmatrix.sync.aligned.m8n8.x4.shared.b16 {%0,%1,%2,%3}, [%4];" \
                 : "=r"(r0), "=r"(r1), "=r"(r2), "=r"(r3) : "r"(addr))

#define LDMATRIX_X4_T(r0, r1, r2, r3, addr)                                   \
    asm volatile("ldmatrix.sync.aligned.m8n8.x4.trans.shared.b16 {%0,%1,%2,%3}, [%4];" \
                 : "=r"(r0), "=r"(r1), "=r"(r2), "=r"(r3) : "r"(addr))

#define MMA_16816(d0, d1, d2, d3, a0, a1, a2, a3, b0, b1)                     \
    asm volatile("mma.sync.aligned.m16n8k16.row.col.f32.f16.f16.f32 "         \
                 "{%0,%1,%2,%3}, {%4,%5,%6,%7}, {%8,%9}, {%0,%1,%2,%3};"       \
                 : "+f"(d0), "+f"(d1), "+f"(d2), "+f"(d3)                      \
                 : "r"(a0), "r"(a1), "r"(a2), "r"(a3), "r"(b0), "r"(b1))

// ---------------- prepass: A f32 -> f16 ----------------
__global__ void convert_A_kernel(const float* __restrict__ A)
{
    size_t idx = ((size_t)blockIdx.x * blockDim.x + threadIdx.x) * 8;
    float4 v0 = *reinterpret_cast<const float4*>(A + idx);
    float4 v1 = *reinterpret_cast<const float4*>(A + idx + 4);
    uint4 h;
    half2 a = __floats2half2_rn(v0.x, v0.y);
    half2 b = __floats2half2_rn(v0.z, v0.w);
    half2 c = __floats2half2_rn(v1.x, v1.y);
    half2 d = __floats2half2_rn(v1.z, v1.w);
    h.x = *reinterpret_cast<unsigned*>(&a);
    h.y = *reinterpret_cast<unsigned*>(&b);
    h.z = *reinterpret_cast<unsigned*>(&c);
    h.w = *reinterpret_cast<unsigned*>(&d);
    *reinterpret_cast<uint4*>(g_A16 + idx) = h;
}

// ---------------- main GEMM ----------------
__global__ __launch_bounds__(256, 2)
void awq_gemm_kernel(const int*   __restrict__ qw,
                     const float* __restrict__ scales,
                     float*       __restrict__ C)
{
    extern __shared__ char smem[];
    const uint32_t sbase = smem_u32(smem);

    const int tid    = threadIdx.x;
    const int lane   = tid & 31;
    const int wid    = tid >> 5;
    const int warp_m = wid & 1;
    const int warp_n = wid >> 1;

    const int m0 = blockIdx.y * BM;
    const int n0 = blockIdx.x * BN;

    const int q_col = tid & 15;   // int32 column within tile
    const int q_row = tid >> 4;   // 0..15 (owns k-rows q_row + 16*r, r=0..3)

    // smem address helpers
#define SA_ADDR(buf, row, col)  (sbase + (buf) * SA_STAGE + (row) * 144 + (col) * 2)
#define SB_ADDR(buf, row, col)  (sbase + SB_BASE + (buf) * SB_STAGE + (row) * 272 + (col) * 2)

    float acc[4][4][4];
    #pragma unroll
    for (int i = 0; i < 4; i++)
        #pragma unroll
        for (int j = 0; j < 4; j++)
            #pragma unroll
            for (int l = 0; l < 4; l++) acc[i][j][l] = 0.0f;

    const half2 MAGIC = __halves2half2(__ushort_as_half(0x6408), __ushort_as_half(0x6408)); // 1032

    const int*   qw_base = qw + (size_t)q_row * PACKED_N + (n0 >> 3) + q_col;
    const float* sc_base = scales + n0 + q_col * 8;

    half2 sc[4];
    // A fill: 1024 x 16B chunks, 4 per thread; chunk c: row=c>>3, col16=c&7
    const int a_row = tid >> 3;
    const int a_col = (tid & 7) * 8;

#define ISSUE_A(k0, buf)                                                       \
    do {                                                                       \
        _Pragma("unroll")                                                      \
        for (int j = 0; j < 4; j++) {                                          \
            int row = a_row + j * 32;                                          \
            unsigned d = SA_ADDR(buf, row, a_col);                             \
            const half* s = g_A16 + (size_t)(m0 + row) * K_DIM + (k0) + a_col; \
            asm volatile("cp.async.cg.shared.global [%0], [%1], 16;\n" :: "r"(d), "l"(s)); \
        }                                                                      \
        asm volatile("cp.async.commit_group;\n");                              \
    } while (0)

#define LOAD_SCALES(g)                                                         \
    do {                                                                       \
        const float* sp = sc_base + (size_t)(g) * N_DIM;                       \
        float4 f0 = *reinterpret_cast<const float4*>(sp);                      \
        float4 f1 = *reinterpret_cast<const float4*>(sp + 4);                  \
        sc[0] = __floats2half2_rn(f0.x, f1.x);                                 \
        sc[1] = __floats2half2_rn(f0.y, f1.y);                                 \
        sc[2] = __floats2half2_rn(f0.z, f1.z);                                 \
        sc[3] = __floats2half2_rn(f0.w, f1.w);                                 \
    } while (0)

#define DEQUANT_STORE(qv, rrow, buf)                                           \
    do {                                                                       \
        unsigned q = (unsigned)(qv);                                           \
        unsigned t0 = ( q        & 0x000F000Fu) | 0x64006400u;                 \
        unsigned t1 = ((q >> 4)  & 0x000F000Fu) | 0x64006400u;                 \
        unsigned t2 = ((q >> 8)  & 0x000F000Fu) | 0x64006400u;                 \
        unsigned t3 = ((q >> 12) & 0x000F000Fu) | 0x64006400u;                 \
        half2 v0 = __hmul2(__hsub2(*reinterpret_cast<half2*>(&t0), MAGIC), sc[0]); \
        half2 v1 = __hmul2(__hsub2(*reinterpret_cast<half2*>(&t1), MAGIC), sc[1]); \
        half2 v2 = __hmul2(__hsub2(*reinterpret_cast<half2*>(&t2), MAGIC), sc[2]); \
        half2 v3 = __hmul2(__hsub2(*reinterpret_cast<half2*>(&t3), MAGIC), sc[3]); \
        half2 p01 = __halves2half2(__low2half(v0),  __low2half(v1));           \
        half2 p23 = __halves2half2(__low2half(v2),  __low2half(v3));           \
        half2 p45 = __halves2half2(__high2half(v0), __high2half(v1));          \
        half2 p67 = __halves2half2(__high2half(v2), __high2half(v3));          \
        uint4 packed;                                                          \
        packed.x = *reinterpret_cast<unsigned*>(&p01);                         \
        packed.y = *reinterpret_cast<unsigned*>(&p23);                         \
        packed.z = *reinterpret_cast<unsigned*>(&p45);                         \
        packed.w = *reinterpret_cast<unsigned*>(&p67);                         \
        asm volatile("st.shared.v4.b32 [%0], {%1, %2, %3, %4};"                \
                     :: "r"(SB_ADDR(buf, rrow, q_col * 8)),                    \
                        "r"(packed.x), "r"(packed.y), "r"(packed.z), "r"(packed.w) \
                     : "memory");                                              \
    } while (0)

#define MMA_KSTEP(ks, buf)                                                     \
    do {                                                                       \
        unsigned a[4][4];                                                      \
        _Pragma("unroll")                                                      \
        for (int mf = 0; mf < 4; mf++) {                                       \
            int row = warp_m * 64 + mf * 16 + (lane & 15);                     \
            int col = (ks) * 16 + (lane >> 4) * 8;                             \
            unsigned addr = SA_ADDR(buf, row, col);                            \
            LDMATRIX_X4(a[mf][0], a[mf][1], a[mf][2], a[mf][3], addr);         \
        }                                                                      \
        unsigned bfr[4][2];                                                    \
        _Pragma("unroll")                                                      \
        for (int p = 0; p < 2; p++) {                                          \
            int row = (ks) * 16 + (lane & 15);                                 \
            int col = warp_n * 32 + p * 16 + (lane >> 4) * 8;                  \
            unsigned addr = SB_ADDR(buf, row, col);                            \
            unsigned r0, r1, r2, r3;                                           \
            LDMATRIX_X4_T(r0, r1, r2, r3, addr);                               \
            bfr[p * 2 + 0][0] = r0; bfr[p * 2 + 0][1] = r1;                    \
            bfr[p * 2 + 1][0] = r2; bfr[p * 2 + 1][1] = r3;                    \
        }                                                                      \
        _Pragma("unroll")                                                      \
        for (int mf = 0; mf < 4; mf++)                                         \
            _Pragma("unroll")                                                  \
            for (int nf = 0; nf < 4; nf++)                                     \
                MMA_16816(acc[mf][nf][0], acc[mf][nf][1], acc[mf][nf][2], acc[mf][nf][3], \
                          a[mf][0], a[mf][1], a[mf][2], a[mf][3],              \
                          bfr[nf][0], bfr[nf][1]);                             \
    } while (0)

    // ---- prologue: fill stage 0 ----
    ISSUE_A(0, 0);
    LOAD_SCALES(0);
    {
        const int* qp = qw_base;
        int w0 = qp[0];
        int w1 = qp[(size_t)16 * PACKED_N];
        int w2 = qp[(size_t)32 * PACKED_N];
        int w3 = qp[(size_t)48 * PACKED_N];
        DEQUANT_STORE(w0, q_row,      0);
        DEQUANT_STORE(w1, q_row + 16, 0);
        DEQUANT_STORE(w2, q_row + 32, 0);
        DEQUANT_STORE(w3, q_row + 48, 0);
    }
    asm volatile("cp.async.wait_group 0;\n");
    __syncthreads();

    int cur = 0;
    for (int i = 0; i < K_TILES; i++) {
        const int nxt = cur ^ 1;
        const int k1  = (i + 1) * BK;
        const bool has_next = (i + 1 < K_TILES);

        int nw0 = 0, nw1 = 0, nw2 = 0, nw3 = 0;
        if (has_next) {
            ISSUE_A(k1, nxt);
            const int* qp = qw_base + (size_t)k1 * PACKED_N;
            nw0 = qp[0];
            nw1 = qp[(size_t)16 * PACKED_N];
            nw2 = qp[(size_t)32 * PACKED_N];
            nw3 = qp[(size_t)48 * PACKED_N];
        }

        MMA_KSTEP(0, cur);
        MMA_KSTEP(1, cur);
        MMA_KSTEP(2, cur);

        // dequant for next tile, overlapped with remaining MMA
        if (has_next) {
            if ((k1 & 127) == 0) LOAD_SCALES(k1 >> 7);
            DEQUANT_STORE(nw0, q_row,      nxt);
            DEQUANT_STORE(nw1, q_row + 16, nxt);
            DEQUANT_STORE(nw2, q_row + 32, nxt);
            DEQUANT_STORE(nw3, q_row + 48, nxt);
        }

        MMA_KSTEP(3, cur);

        if (has_next) asm volatile("cp.async.wait_group 0;\n");
        __syncthreads();
        cur = nxt;
    }

    // ---- epilogue: round to f16 grid, store f32 ----
    const int r  = lane >> 2;
    const int cp = (lane & 3) * 2;
    #pragma unroll
    for (int mf = 0; mf < 4; mf++) {
        const int row_base = m0 + warp_m * 64 + mf * 16;
        #pragma unroll
        for (int nf = 0; nf < 4; nf++) {
            const int col = n0 + warp_n * 32 + nf * 8 + cp;
            float2 lo, hi;
            lo.x = __half2float(__float2half_rn(acc[mf][nf][0]));
            lo.y = __half2float(__float2half_rn(acc[mf][nf][1]));
            hi.x = __half2float(__float2half_rn(acc[mf][nf][2]));
            hi.y = __half2float(__float2half_rn(acc[mf][nf][3]));
            *reinterpret_cast<float2*>(C + (size_t)(row_base + r)     * N_DIM + col) = lo;
            *reinterpret_cast<float2*>(C + (size_t)(row_base + r + 8) * N_DIM + col) = hi;
        }
    }
}

extern "C" void kernel_launch(void* const* d_in, const int* in_sizes, int n_in,
                              void* d_out, int out_size)
{
    const float* A      = (const float*)d_in[0];
    const int*   qw     = (const int*)d_in[1];
    const float* scales = (const float*)d_in[2];
    float*       C      = (float*)d_out;

    const size_t total = (size_t)M_TOTAL * K_DIM;
    convert_A_kernel<<<(unsigned)(total / 2048), 256>>>(A);

    cudaFuncSetAttribute(awq_gemm_kernel,
                         cudaFuncAttributeMaxDynamicSharedMemorySize, SMEM_TOTAL);
    dim3 grid(N_DIM / BN, M_TOTAL / BM);   // (86, 32)
    awq_gemm_kernel<<<grid, 256, SMEM_TOTAL>>>(qw, scales, C);
}